// round 9
// baseline (speedup 1.0000x reference)
#include <cuda_runtime.h>
#include <cuda_bf16.h>
#include <cstdint>

#define N_ROWS 65536
#define D      64
#define NE     1024
#define M_TILE 128                     // rows per CTA (8 warps x m16)
#define NC     64                      // codes per chunk
#define NUM_CHUNKS (NE / NC)           // 16
#define GRID_MAIN (N_ROWS / M_TILE)    // 512
#define GAP_THRESH 2e-4f
#define REFINE_BLOCKS 256
#define REFINE_THREADS 128
#define K3_THREADS 256
#define K3_BLOCKS  (N_ROWS * 4 / K3_THREADS)   // 1024
#define BSTRIDE 80                     // padded smem row stride in BYTES (64 data + 16 pad)
#define S2_SCALE 32512.0f              // 127*256 (|e| <= 1/256)
#define INV_DENOM (1.0f / (128.0f * 127.0f * S2_SCALE))

// ---------------- scratch (no allocations allowed) ----------------
__device__ float g_e2[NE];
__device__ __align__(16) signed char g_eA[NE * D];   // e hi plane (int8)
__device__ __align__(16) signed char g_eB[NE * D];   // e lo plane (int8)
__device__ int   g_idx[N_ROWS];
__device__ float g_partial[GRID_MAIN];
__device__ int   g_flag_cnt;
__device__ int   g_flag_rows[N_ROWS];

// ---------------- helpers ----------------
__device__ __forceinline__ uint32_t smem_u32(const void* p) {
    uint32_t a;
    asm("{ .reg .u64 t; cvta.to.shared.u64 t, %1; cvt.u32.u64 %0, t; }"
        : "=r"(a) : "l"(p));
    return a;
}
__device__ __forceinline__ uint32_t pack4(int a, int b, int c, int d) {
    return (uint32_t)(a & 0xFF) | ((uint32_t)(b & 0xFF) << 8) |
           ((uint32_t)(c & 0xFF) << 16) | ((uint32_t)(d & 0xFF) << 24);
}
__device__ __forceinline__ void imma_s8(int& c0, int& c1, int& c2, int& c3,
                                        uint32_t a0, uint32_t a1, uint32_t a2, uint32_t a3,
                                        uint32_t b0, uint32_t b1) {
    asm volatile(
        "mma.sync.aligned.m16n8k32.row.col.s32.s8.s8.s32 "
        "{%0,%1,%2,%3}, {%4,%5,%6,%7}, {%8,%9}, {%0,%1,%2,%3};"
        : "+r"(c0), "+r"(c1), "+r"(c2), "+r"(c3)
        : "r"(a0), "r"(a1), "r"(a2), "r"(a3), "r"(b0), "r"(b1));
}
__device__ __forceinline__ void ldsm_x2(uint32_t& r0, uint32_t& r1, uint32_t addr) {
    asm volatile("ldmatrix.sync.aligned.m8n8.x2.shared.b16 {%0,%1}, [%2];"
                 : "=r"(r0), "=r"(r1) : "r"(addr));
}
// merge two (best, best2, idx) candidate sets (union top-2), min-index tiebreak
__device__ __forceinline__ void merge_top2(float& b, float& b2, int& i, int off) {
    float ob  = __shfl_xor_sync(0xffffffffu, b,  off);
    float ob2 = __shfl_xor_sync(0xffffffffu, b2, off);
    int   oi  = __shfl_xor_sync(0xffffffffu, i,  off);
    int   ni  = (ob < b || (ob == b && oi < i)) ? oi : i;
    float nb2 = fminf(fmaxf(b, ob), fminf(b2, ob2));
    b  = fminf(b, ob);
    b2 = nb2;
    i  = ni;
}

// ---------------------------------------------------------------------------
// Kernel 1: per-code prep: e2 (fp32), int8 dual-plane quantization of e.
// e ~ (a + b/128) / S2, a,b int8 (|a|<=127, |b|<=64). + reset flag counter.
// ---------------------------------------------------------------------------
__global__ void prep_kernel(const float* __restrict__ emb) {
    int j = blockIdx.x * blockDim.x + threadIdx.x;
    if (j == 0) g_flag_cnt = 0;
    if (j < NE) {
        const float* e = emb + (size_t)j * D;
        float s = 0.f;
        #pragma unroll
        for (int k = 0; k < D; k++) {
            float v = e[k];
            s += v * v;
            float f = v * S2_SCALE;
            int a = __float2int_rn(f);
            int b = __float2int_rn((f - (float)a) * 128.f);
            g_eA[j * D + k] = (signed char)a;
            g_eB[j * D + k] = (signed char)b;
        }
        g_e2[j] = s;
    }
}

// ---------------------------------------------------------------------------
// Kernel 2: IMMA argmin via mma.sync m16n8k32 s8 (2x MAC rate vs bf16 HMMA).
// CTA = 8 warps x m16 rows. z quantized per-row into 2 int8 planes
// (a + b/128)/s1 with s1 = 127/rowmax (row-constant scale divides out).
// dot*(128*s1*S2) = 128*ACC1 + ACC2 where ACC1 = a_z.a_e (s32 exact),
// ACC2 = a_z.b_e + b_z.a_e. 3 IMMA per k32-step, 6 per n-tile (vs 12 HMMA).
// |d error| <~4e-5 worst-case << GAP_THRESH=2e-4 -> near-ties refined exactly.
// ---------------------------------------------------------------------------
__global__ __launch_bounds__(256, 2)
void argmin_tc_kernel(const float* __restrict__ z,
                      float* __restrict__ idx_out_f) {
    __shared__ __align__(16) signed char sBA[NC * BSTRIDE];   // 5 KB
    __shared__ __align__(16) signed char sBB[NC * BSTRIDE];   // 5 KB
    __shared__ float sE2[NC];
    __shared__ float sLoss[8];

    int tid  = threadIdx.x;
    int wid  = tid >> 5;
    int lane = tid & 31;
    int grp  = lane >> 2;         // row within m16 tile (0..7)
    int c    = lane & 3;          // k/col quad

    // ---- load z rows, exact fp32 z2, rowmax, dual-plane int8 A fragments ----
    int rbase = blockIdx.x * M_TILE + wid * 16;
    int r0 = rbase + grp;                       // rows r0 and r0+8
    float4 v0[4], v1[4];                        // [t] -> dims t*16 + 4c .. +3
    {
        const float* zr0 = z + (size_t)r0 * D;
        const float* zr1 = zr0 + 8 * D;
        #pragma unroll
        for (int t = 0; t < 4; t++) {
            v0[t] = *(const float4*)(zr0 + 16 * t + 4 * c);
            v1[t] = *(const float4*)(zr1 + 16 * t + 4 * c);
        }
    }
    float z2_0 = 0.f, z2_1 = 0.f, mx0 = 0.f, mx1 = 0.f;
    #pragma unroll
    for (int t = 0; t < 4; t++) {
        z2_0 += v0[t].x * v0[t].x + v0[t].y * v0[t].y + v0[t].z * v0[t].z + v0[t].w * v0[t].w;
        z2_1 += v1[t].x * v1[t].x + v1[t].y * v1[t].y + v1[t].z * v1[t].z + v1[t].w * v1[t].w;
        mx0 = fmaxf(mx0, fmaxf(fmaxf(fabsf(v0[t].x), fabsf(v0[t].y)),
                               fmaxf(fabsf(v0[t].z), fabsf(v0[t].w))));
        mx1 = fmaxf(mx1, fmaxf(fmaxf(fabsf(v1[t].x), fabsf(v1[t].y)),
                               fmaxf(fabsf(v1[t].z), fabsf(v1[t].w))));
    }
    #pragma unroll
    for (int o = 1; o <= 2; o <<= 1) {
        z2_0 += __shfl_xor_sync(0xffffffffu, z2_0, o);
        z2_1 += __shfl_xor_sync(0xffffffffu, z2_1, o);
        mx0 = fmaxf(mx0, __shfl_xor_sync(0xffffffffu, mx0, o));
        mx1 = fmaxf(mx1, __shfl_xor_sync(0xffffffffu, mx1, o));
    }
    mx0 = fmaxf(mx0, 1e-20f);
    mx1 = fmaxf(mx1, 1e-20f);
    float s1_0 = 127.f / mx0, s1_1 = 127.f / mx1;
    float invc0 = mx0 * INV_DENOM, invc1 = mx1 * INV_DENOM;

    uint32_t pa0[4], pb0[4], pa1[4], pb1[4];    // [t] packed int8x4 per plane/row
    #pragma unroll
    for (int t = 0; t < 4; t++) {
        float f; int ax, ay, az, aw, bx, by, bz, bw;
        f = v0[t].x * s1_0; ax = __float2int_rn(f); bx = __float2int_rn((f - (float)ax) * 128.f);
        f = v0[t].y * s1_0; ay = __float2int_rn(f); by = __float2int_rn((f - (float)ay) * 128.f);
        f = v0[t].z * s1_0; az = __float2int_rn(f); bz = __float2int_rn((f - (float)az) * 128.f);
        f = v0[t].w * s1_0; aw = __float2int_rn(f); bw = __float2int_rn((f - (float)aw) * 128.f);
        pa0[t] = pack4(ax, ay, az, aw); pb0[t] = pack4(bx, by, bz, bw);
        f = v1[t].x * s1_1; ax = __float2int_rn(f); bx = __float2int_rn((f - (float)ax) * 128.f);
        f = v1[t].y * s1_1; ay = __float2int_rn(f); by = __float2int_rn((f - (float)ay) * 128.f);
        f = v1[t].z * s1_1; az = __float2int_rn(f); bz = __float2int_rn((f - (float)az) * 128.f);
        f = v1[t].w * s1_1; aw = __float2int_rn(f); bw = __float2int_rn((f - (float)aw) * 128.f);
        pa1[t] = pack4(ax, ay, az, aw); pb1[t] = pack4(bx, by, bz, bw);
    }

    float b0 = 3.402823466e38f, b20 = 3.402823466e38f;  // row r0
    float b1 = 3.402823466e38f, b21 = 3.402823466e38f;  // row r0+8
    int   i0 = 0, i1 = 0;

    uint32_t sba = smem_u32(sBA);
    uint32_t sbb = smem_u32(sBB);
    int ll = lane & 15;
    uint32_t lrow = (uint32_t)(ll & 7) * BSTRIDE + ((uint32_t)(ll >> 3)) * 16;

    for (int ch = 0; ch < NUM_CHUNKS; ch++) {
        int cbase = ch * NC;
        __syncthreads();
        // ---- stage B chunk (both planes) + e2 ----
        {
            int row = tid >> 2, q = tid & 3;     // 64 rows x 4 x 16B
            *(uint4*)(sBA + row * BSTRIDE + q * 16) =
                *(const uint4*)(g_eA + (size_t)(cbase + row) * D + q * 16);
            *(uint4*)(sBB + row * BSTRIDE + q * 16) =
                *(const uint4*)(g_eB + (size_t)(cbase + row) * D + q * 16);
            if (tid < NC) sE2[tid] = g_e2[cbase + tid];
        }
        __syncthreads();

        #pragma unroll 1
        for (int nt = 0; nt < NC / 8; nt++) {
            int acc1_0 = 0, acc1_1 = 0, acc1_2 = 0, acc1_3 = 0;
            int acc2_0 = 0, acc2_1 = 0, acc2_2 = 0, acc2_3 = 0;
            uint32_t nbase = (uint32_t)(nt * 8) * BSTRIDE + lrow;
            #pragma unroll
            for (int ks = 0; ks < 2; ks++) {     // k bytes 32*ks .. +31
                uint32_t ba0, ba1, bb0, bb1;
                ldsm_x2(ba0, ba1, sba + nbase + ks * 32);
                ldsm_x2(bb0, bb1, sbb + nbase + ks * 32);
                // A regs for this k-step: {row0 t=2ks, row1 t=2ks, row0 t=2ks+1, row1 t=2ks+1}
                imma_s8(acc1_0, acc1_1, acc1_2, acc1_3,
                        pa0[2*ks], pa1[2*ks], pa0[2*ks+1], pa1[2*ks+1], ba0, ba1);
                imma_s8(acc2_0, acc2_1, acc2_2, acc2_3,
                        pa0[2*ks], pa1[2*ks], pa0[2*ks+1], pa1[2*ks+1], bb0, bb1);
                imma_s8(acc2_0, acc2_1, acc2_2, acc2_3,
                        pb0[2*ks], pb1[2*ks], pb0[2*ks+1], pb1[2*ks+1], ba0, ba1);
            }
            // ---- epilogue: dot = (128*ACC1 + ACC2) * invc ----
            float dot0 = fmaf((float)acc1_0, 128.f, (float)acc2_0) * invc0;
            float dot1 = fmaf((float)acc1_1, 128.f, (float)acc2_1) * invc0;
            float dot2 = fmaf((float)acc1_2, 128.f, (float)acc2_2) * invc1;
            float dot3 = fmaf((float)acc1_3, 128.f, (float)acc2_3) * invc1;
            int ca = cbase + nt * 8 + 2 * c;
            float ea = sE2[nt * 8 + 2 * c];
            float eb = sE2[nt * 8 + 2 * c + 1];
            float dd0 = (z2_0 + ea) - 2.f * dot0;
            float dd1 = (z2_0 + eb) - 2.f * dot1;
            float dd2 = (z2_1 + ea) - 2.f * dot2;
            float dd3 = (z2_1 + eb) - 2.f * dot3;
            if (dd0 < b0) { b20 = b0; b0 = dd0; i0 = ca; }
            else if (dd0 < b20) b20 = dd0;
            if (dd1 < b0) { b20 = b0; b0 = dd1; i0 = ca + 1; }
            else if (dd1 < b20) b20 = dd1;
            if (dd2 < b1) { b21 = b1; b1 = dd2; i1 = ca; }
            else if (dd2 < b21) b21 = dd2;
            if (dd3 < b1) { b21 = b1; b1 = dd3; i1 = ca + 1; }
            else if (dd3 < b21) b21 = dd3;
        }
    }

    // ---- merge across the 4 lanes of each row group ----
    merge_top2(b0, b20, i0, 1); merge_top2(b0, b20, i0, 2);
    merge_top2(b1, b21, i1, 1); merge_top2(b1, b21, i1, 2);

    if (c == 0) {
        int r1 = r0 + 8;
        g_idx[r0] = i0;            g_idx[r1] = i1;
        idx_out_f[r0] = (float)i0; idx_out_f[r1] = (float)i1;
        if (b20 - b0 < GAP_THRESH) { int s = atomicAdd(&g_flag_cnt, 1); g_flag_rows[s] = r0; }
        if (b21 - b1 < GAP_THRESH) { int s = atomicAdd(&g_flag_cnt, 1); g_flag_rows[s] = r1; }
    }

    // ---- loss partial: sum of bestd over the CTA's 128 rows ----
    float v = (c == 0) ? (b0 + b1) : 0.f;
    #pragma unroll
    for (int o = 16; o > 0; o >>= 1) v += __shfl_down_sync(0xffffffffu, v, o);
    if (lane == 0) sLoss[wid] = v;
    __syncthreads();
    if (tid == 0) {
        float s = 0.f;
        #pragma unroll
        for (int w = 0; w < 8; w++) s += sLoss[w];
        g_partial[blockIdx.x] = s;
    }
}

// ---------------------------------------------------------------------------
// Kernel 2b: refine flagged rows with Kahan-compensated exact fp32 dots;
// rewrites g_idx + idx_out only (gather re-reads g_idx afterwards).
// ---------------------------------------------------------------------------
__global__ __launch_bounds__(REFINE_THREADS)
void refine_kernel(const float* __restrict__ z,
                   const float* __restrict__ emb,
                   float* __restrict__ idx_out_f) {
    __shared__ float sz[D];
    __shared__ float sd[REFINE_THREADS];
    __shared__ int   si[REFINE_THREADS];

    int cnt = g_flag_cnt;
    for (int w = blockIdx.x; w < cnt; w += gridDim.x) {
        int row = g_flag_rows[w];

        __syncthreads();
        if (threadIdx.x < D) sz[threadIdx.x] = z[(size_t)row * D + threadIdx.x];
        __syncthreads();

        float z2 = 0.f;
        #pragma unroll
        for (int k = 0; k < D; k++) z2 += sz[k] * sz[k];

        float bestd = 3.402823466e38f;
        int   besti = NE;

        for (int j = threadIdx.x; j < NE; j += REFINE_THREADS) {
            const float4* e = (const float4*)(emb + (size_t)j * D);
            float4 ev[16];
            #pragma unroll
            for (int q = 0; q < 16; q++) ev[q] = e[q];

            float s = 0.f, cc = 0.f;
            #pragma unroll
            for (int q = 0; q < 16; q++) {
                float el[4] = {ev[q].x, ev[q].y, ev[q].z, ev[q].w};
                #pragma unroll
                for (int u = 0; u < 4; u++) {
                    float p = __fmul_rn(sz[q * 4 + u], el[u]);
                    float y = __fadd_rn(p, -cc);
                    float t = __fadd_rn(s, y);
                    cc = __fadd_rn(__fadd_rn(t, -s), -y);
                    s = t;
                }
            }
            float dot = __fadd_rn(s, cc);
            float dd  = __fadd_rn(__fadd_rn(z2, g_e2[j]), -2.f * dot);
            if (dd < bestd || (dd == bestd && j < besti)) { bestd = dd; besti = j; }
        }

        sd[threadIdx.x] = bestd;
        si[threadIdx.x] = besti;
        __syncthreads();
        #pragma unroll
        for (int st = REFINE_THREADS / 2; st > 0; st >>= 1) {
            if (threadIdx.x < st) {
                float od = sd[threadIdx.x + st];
                int   oi = si[threadIdx.x + st];
                if (od < sd[threadIdx.x] ||
                    (od == sd[threadIdx.x] && oi < si[threadIdx.x])) {
                    sd[threadIdx.x] = od;
                    si[threadIdx.x] = oi;
                }
            }
            __syncthreads();
        }
        if (threadIdx.x == 0) {
            g_idx[row]     = si[0];
            idx_out_f[row] = (float)si[0];
        }
        __syncthreads();
    }
}

// ---------------------------------------------------------------------------
// Kernel 3: zq gather, 4 threads/row. out = z + (e - z) (straight-through).
// zq_out only 4B-aligned -> scalar stores.
// ---------------------------------------------------------------------------
__global__ __launch_bounds__(K3_THREADS)
void gather_kernel(const float* __restrict__ z,
                   const float* __restrict__ emb,
                   float* __restrict__ zq_out) {
    int gt   = blockIdx.x * K3_THREADS + threadIdx.x;
    int row  = gt >> 2;
    int part = gt & 3;
    int j    = g_idx[row];

    const float4* ef = (const float4*)(emb + (size_t)j * D + part * 16);
    const float4* zf = (const float4*)(z + (size_t)row * D + part * 16);
    float*        o  = zq_out + (size_t)row * D + part * 16;

    #pragma unroll
    for (int q = 0; q < 4; q++) {
        float4 e  = ef[q];
        float4 zv = zf[q];
        o[q * 4 + 0] = __fadd_rn(zv.x, __fadd_rn(e.x, -zv.x));
        o[q * 4 + 1] = __fadd_rn(zv.y, __fadd_rn(e.y, -zv.y));
        o[q * 4 + 2] = __fadd_rn(zv.z, __fadd_rn(e.z, -zv.z));
        o[q * 4 + 3] = __fadd_rn(zv.w, __fadd_rn(e.w, -zv.w));
    }
}

// ---------------------------------------------------------------------------
// Kernel 4: final loss reduction over 512 partials.
// loss = 1.25 * sum / (N*D)
// ---------------------------------------------------------------------------
__global__ void final_kernel(float* __restrict__ out) {
    __shared__ float red[256];
    red[threadIdx.x] = g_partial[threadIdx.x] + g_partial[threadIdx.x + 256];
    __syncthreads();
    #pragma unroll
    for (int st = 128; st > 0; st >>= 1) {
        if (threadIdx.x < st) red[threadIdx.x] += red[threadIdx.x + st];
        __syncthreads();
    }
    if (threadIdx.x == 0)
        out[0] = 1.25f * red[0] / (float)(N_ROWS * D);
}

// ---------------------------------------------------------------------------
// Launch: out layout = [loss(1) | z_q(N_ROWS*D) | indices(N_ROWS)] fp32
// ---------------------------------------------------------------------------
extern "C" void kernel_launch(void* const* d_in, const int* in_sizes, int n_in,
                              void* d_out, int out_size) {
    const float* z   = (const float*)d_in[0];
    const float* emb = (const float*)d_in[1];
    float* out     = (float*)d_out;
    float* zq_out  = out + 1;
    float* idx_out = out + 1 + (size_t)N_ROWS * D;

    prep_kernel<<<4, 256>>>(emb);
    argmin_tc_kernel<<<GRID_MAIN, 256>>>(z, idx_out);
    refine_kernel<<<REFINE_BLOCKS, REFINE_THREADS>>>(z, emb, idx_out);
    gather_kernel<<<K3_BLOCKS, K3_THREADS>>>(z, emb, zq_out);
    final_kernel<<<1, 256>>>(out);
}

// round 10
// speedup vs baseline: 1.1574x; 1.1574x over previous
#include <cuda_runtime.h>
#include <cuda_bf16.h>
#include <cstdint>

#define N_ROWS 65536
#define D      64
#define NE     1024
#define M_TILE 128                     // rows per CTA (8 warps x m16)
#define NC     64                      // codes per chunk
#define NUM_CHUNKS (NE / NC)           // 16
#define GRID_MAIN (N_ROWS / M_TILE)    // 512
#define GAP_THRESH 4e-4f
#define REFINE_BLOCKS 256
#define REFINE_THREADS 128
#define K3_THREADS 256
#define K3_BLOCKS  (N_ROWS * 4 / K3_THREADS)   // 1024
#define BSTRIDE 72                     // padded smem row stride (elems) = 144 B

// ---------------- scratch (no allocations allowed) ----------------
__device__ float g_e2[NE];
__device__ __align__(16) __nv_bfloat16 g_ehi[NE * D];
__device__ int   g_idx[N_ROWS];
__device__ float g_partial[GRID_MAIN];
__device__ int   g_flag_cnt;
__device__ int   g_flag_rows[N_ROWS];

// ---------------- helpers ----------------
__device__ __forceinline__ uint32_t smem_u32(const void* p) {
    uint32_t a;
    asm("{ .reg .u64 t; cvta.to.shared.u64 t, %1; cvt.u32.u64 %0, t; }"
        : "=r"(a) : "l"(p));
    return a;
}
__device__ __forceinline__ uint32_t bfpair(__nv_bfloat16 a, __nv_bfloat16 b) {
    __nv_bfloat162 t(a, b);            // a = low 16 bits
    return *reinterpret_cast<uint32_t*>(&t);
}
__device__ __forceinline__ void mma_bf16(float& d0, float& d1, float& d2, float& d3,
                                         uint32_t a0, uint32_t a1, uint32_t a2, uint32_t a3,
                                         uint32_t b0, uint32_t b1) {
    asm volatile(
        "mma.sync.aligned.m16n8k16.row.col.f32.bf16.bf16.f32 "
        "{%0,%1,%2,%3}, {%4,%5,%6,%7}, {%8,%9}, {%0,%1,%2,%3};"
        : "+f"(d0), "+f"(d1), "+f"(d2), "+f"(d3)
        : "r"(a0), "r"(a1), "r"(a2), "r"(a3), "r"(b0), "r"(b1));
}
__device__ __forceinline__ void ldsm_x2(uint32_t& r0, uint32_t& r1, uint32_t addr) {
    asm volatile("ldmatrix.sync.aligned.m8n8.x2.shared.b16 {%0,%1}, [%2];"
                 : "=r"(r0), "=r"(r1) : "r"(addr));
}
// merge two (best, best2, idx) candidate sets (union top-2), min-index tiebreak
__device__ __forceinline__ void merge_top2(float& b, float& b2, int& i, int off) {
    float ob  = __shfl_xor_sync(0xffffffffu, b,  off);
    float ob2 = __shfl_xor_sync(0xffffffffu, b2, off);
    int   oi  = __shfl_xor_sync(0xffffffffu, i,  off);
    int   ni  = (ob < b || (ob == b && oi < i)) ? oi : i;
    float nb2 = fminf(fmaxf(b, ob), fminf(b2, ob2));
    b  = fminf(b, ob);
    b2 = nb2;
    i  = ni;
}

// ---------------------------------------------------------------------------
// Kernel 1: per-code prep: e2 (fp32) + bf16 e. + reset flag counter.
// ---------------------------------------------------------------------------
__global__ void prep_kernel(const float* __restrict__ emb) {
    int j = blockIdx.x * blockDim.x + threadIdx.x;
    if (j == 0) g_flag_cnt = 0;
    if (j < NE) {
        const float* e = emb + (size_t)j * D;
        float s = 0.f;
        #pragma unroll
        for (int k = 0; k < D; k++) {
            float v = e[k];
            s += v * v;
            g_ehi[j * D + k] = __float2bfloat16_rn(v);
        }
        g_e2[j] = s;
    }
}

// ---------------------------------------------------------------------------
// Kernel 2: HMMA argmin via mma.sync m16n8k16 bf16.
// dot = (Zhi + Zlo) . Bhi  -- z side exact via 2-plane bf16 split (8 MMAs +
// 4 ldsm per n-tile, vs round-8's 12+8). Remaining error = e's bf16
// quantization only: sigma(delta d) ~ 7e-5 per candidate pair; GAP=4e-4=8sigma
// -> near-ties go to exact refine, flip risk ~1e-15.
// ---------------------------------------------------------------------------
__global__ __launch_bounds__(256, 2)
void argmin_tc_kernel(const float* __restrict__ z,
                      float* __restrict__ idx_out_f) {
    __shared__ __align__(16) __nv_bfloat16 sBhi[NC * BSTRIDE];  // 9.2 KB
    __shared__ float sE2[NC];
    __shared__ float sLoss[8];

    int tid  = threadIdx.x;
    int wid  = tid >> 5;
    int lane = tid & 31;
    int grp  = lane >> 2;         // 0..7  (row within tile)
    int c    = lane & 3;          // 0..3  (pair column)

    // ---- A fragments (hi/lo) straight from gmem; z2 per row via group shfl ----
    int rbase = blockIdx.x * M_TILE + wid * 16;
    int r0 = rbase + grp;         // rows grp and grp+8 of this warp's m16 tile
    uint32_t ahi[16], alo[16];
    float z2_0 = 0.f, z2_1 = 0.f;
    {
        const float* zr0 = z + (size_t)r0 * D;
        const float* zr1 = zr0 + 8 * D;
        #pragma unroll
        for (int t = 0; t < 4; t++) {
            float2 p0 = *(const float2*)(zr0 + 16 * t + 2 * c);
            float2 p1 = *(const float2*)(zr1 + 16 * t + 2 * c);
            float2 p2 = *(const float2*)(zr0 + 16 * t + 8 + 2 * c);
            float2 p3 = *(const float2*)(zr1 + 16 * t + 8 + 2 * c);
            z2_0 += p0.x * p0.x + p0.y * p0.y + p2.x * p2.x + p2.y * p2.y;
            z2_1 += p1.x * p1.x + p1.y * p1.y + p3.x * p3.x + p3.y * p3.y;
            float2 ps[4] = {p0, p1, p2, p3};
            #pragma unroll
            for (int u = 0; u < 4; u++) {
                __nv_bfloat16 hx = __float2bfloat16_rn(ps[u].x);
                __nv_bfloat16 hy = __float2bfloat16_rn(ps[u].y);
                ahi[t * 4 + u] = bfpair(hx, hy);
                alo[t * 4 + u] = bfpair(
                    __float2bfloat16_rn(ps[u].x - __bfloat162float(hx)),
                    __float2bfloat16_rn(ps[u].y - __bfloat162float(hy)));
            }
        }
        // full-row z2: 4 lanes of the group cover disjoint k's
        z2_0 += __shfl_xor_sync(0xffffffffu, z2_0, 1);
        z2_0 += __shfl_xor_sync(0xffffffffu, z2_0, 2);
        z2_1 += __shfl_xor_sync(0xffffffffu, z2_1, 1);
        z2_1 += __shfl_xor_sync(0xffffffffu, z2_1, 2);
    }

    float b0 = 3.402823466e38f, b20 = 3.402823466e38f;  // row r0
    float b1 = 3.402823466e38f, b21 = 3.402823466e38f;  // row r0+8
    int   i0 = 0, i1 = 0;

    uint32_t sbhi = smem_u32(sBhi);
    // ldmatrix per-lane row address component (lanes 16-31 mirror 0-15)
    int ll = lane & 15;
    uint32_t lrow = (uint32_t)(ll & 7) * (BSTRIDE * 2) + ((uint32_t)(ll >> 3)) * 16;

    for (int ch = 0; ch < NUM_CHUNKS; ch++) {
        int cbase = ch * NC;
        __syncthreads();
        // ---- stage B chunk + e2 ----
        {
            int row = tid >> 2, q = tid & 3;     // 64 rows x 4 quarters
            const uint4* sh = (const uint4*)(g_ehi + (size_t)(cbase + row) * D + q * 16);
            uint4* dh = (uint4*)(sBhi + row * BSTRIDE + q * 16);
            dh[0] = sh[0]; dh[1] = sh[1];
            if (tid < NC) sE2[tid] = g_e2[cbase + tid];
        }
        __syncthreads();

        #pragma unroll 1
        for (int nt = 0; nt < NC / 8; nt++) {
            float d0 = 0.f, d1 = 0.f, d2 = 0.f, d3 = 0.f;
            uint32_t nbase = (uint32_t)(nt * 8) * (BSTRIDE * 2) + lrow;
            #pragma unroll
            for (int t = 0; t < 4; t++) {
                uint32_t bh0, bh1;
                ldsm_x2(bh0, bh1, sbhi + nbase + t * 32);
                mma_bf16(d0, d1, d2, d3, ahi[t*4+0], ahi[t*4+1], ahi[t*4+2], ahi[t*4+3], bh0, bh1);
                mma_bf16(d0, d1, d2, d3, alo[t*4+0], alo[t*4+1], alo[t*4+2], alo[t*4+3], bh0, bh1);
            }
            // ---- epilogue for this n-tile ----
            int ca = cbase + nt * 8 + 2 * c;
            float ea = sE2[nt * 8 + 2 * c];
            float eb = sE2[nt * 8 + 2 * c + 1];
            float dd0 = (z2_0 + ea) - 2.f * d0;
            float dd1 = (z2_0 + eb) - 2.f * d1;
            float dd2 = (z2_1 + ea) - 2.f * d2;
            float dd3 = (z2_1 + eb) - 2.f * d3;
            if (dd0 < b0) { b20 = b0; b0 = dd0; i0 = ca; }
            else if (dd0 < b20) b20 = dd0;
            if (dd1 < b0) { b20 = b0; b0 = dd1; i0 = ca + 1; }
            else if (dd1 < b20) b20 = dd1;
            if (dd2 < b1) { b21 = b1; b1 = dd2; i1 = ca; }
            else if (dd2 < b21) b21 = dd2;
            if (dd3 < b1) { b21 = b1; b1 = dd3; i1 = ca + 1; }
            else if (dd3 < b21) b21 = dd3;
        }
    }

    // ---- merge across the 4 lanes of each row group ----
    merge_top2(b0, b20, i0, 1); merge_top2(b0, b20, i0, 2);
    merge_top2(b1, b21, i1, 1); merge_top2(b1, b21, i1, 2);

    if (c == 0) {
        int r1 = r0 + 8;
        g_idx[r0] = i0;            g_idx[r1] = i1;
        idx_out_f[r0] = (float)i0; idx_out_f[r1] = (float)i1;
        if (b20 - b0 < GAP_THRESH) { int s = atomicAdd(&g_flag_cnt, 1); g_flag_rows[s] = r0; }
        if (b21 - b1 < GAP_THRESH) { int s = atomicAdd(&g_flag_cnt, 1); g_flag_rows[s] = r1; }
    }

    // ---- loss partial: sum of bestd over the CTA's 128 rows ----
    float v = (c == 0) ? (b0 + b1) : 0.f;
    #pragma unroll
    for (int o = 16; o > 0; o >>= 1) v += __shfl_down_sync(0xffffffffu, v, o);
    if (lane == 0) sLoss[wid] = v;
    __syncthreads();
    if (tid == 0) {
        float s = 0.f;
        #pragma unroll
        for (int w = 0; w < 8; w++) s += sLoss[w];
        g_partial[blockIdx.x] = s;
    }
}

// ---------------------------------------------------------------------------
// Kernel 2b: refine flagged rows with Kahan-compensated exact fp32 dots;
// rewrites g_idx + idx_out only (gather re-reads g_idx afterwards).
// ---------------------------------------------------------------------------
__global__ __launch_bounds__(REFINE_THREADS)
void refine_kernel(const float* __restrict__ z,
                   const float* __restrict__ emb,
                   float* __restrict__ idx_out_f) {
    __shared__ float sz[D];
    __shared__ float sd[REFINE_THREADS];
    __shared__ int   si[REFINE_THREADS];

    int cnt = g_flag_cnt;
    for (int w = blockIdx.x; w < cnt; w += gridDim.x) {
        int row = g_flag_rows[w];

        __syncthreads();
        if (threadIdx.x < D) sz[threadIdx.x] = z[(size_t)row * D + threadIdx.x];
        __syncthreads();

        float z2 = 0.f;
        #pragma unroll
        for (int k = 0; k < D; k++) z2 += sz[k] * sz[k];

        float bestd = 3.402823466e38f;
        int   besti = NE;

        for (int j = threadIdx.x; j < NE; j += REFINE_THREADS) {
            const float4* e = (const float4*)(emb + (size_t)j * D);
            float4 ev[16];
            #pragma unroll
            for (int q = 0; q < 16; q++) ev[q] = e[q];

            float s = 0.f, cc = 0.f;
            #pragma unroll
            for (int q = 0; q < 16; q++) {
                float el[4] = {ev[q].x, ev[q].y, ev[q].z, ev[q].w};
                #pragma unroll
                for (int u = 0; u < 4; u++) {
                    float p = __fmul_rn(sz[q * 4 + u], el[u]);
                    float y = __fadd_rn(p, -cc);
                    float t = __fadd_rn(s, y);
                    cc = __fadd_rn(__fadd_rn(t, -s), -y);
                    s = t;
                }
            }
            float dot = __fadd_rn(s, cc);
            float dd  = __fadd_rn(__fadd_rn(z2, g_e2[j]), -2.f * dot);
            if (dd < bestd || (dd == bestd && j < besti)) { bestd = dd; besti = j; }
        }

        sd[threadIdx.x] = bestd;
        si[threadIdx.x] = besti;
        __syncthreads();
        #pragma unroll
        for (int st = REFINE_THREADS / 2; st > 0; st >>= 1) {
            if (threadIdx.x < st) {
                float od = sd[threadIdx.x + st];
                int   oi = si[threadIdx.x + st];
                if (od < sd[threadIdx.x] ||
                    (od == sd[threadIdx.x] && oi < si[threadIdx.x])) {
                    sd[threadIdx.x] = od;
                    si[threadIdx.x] = oi;
                }
            }
            __syncthreads();
        }
        if (threadIdx.x == 0) {
            g_idx[row]     = si[0];
            idx_out_f[row] = (float)si[0];
        }
        __syncthreads();
    }
}

// ---------------------------------------------------------------------------
// Kernel 3: zq gather, 4 threads/row. out = z + (e - z) (straight-through).
// zq_out only 4B-aligned -> scalar stores.
// ---------------------------------------------------------------------------
__global__ __launch_bounds__(K3_THREADS)
void gather_kernel(const float* __restrict__ z,
                   const float* __restrict__ emb,
                   float* __restrict__ zq_out) {
    int gt   = blockIdx.x * K3_THREADS + threadIdx.x;
    int row  = gt >> 2;
    int part = gt & 3;
    int j    = g_idx[row];

    const float4* ef = (const float4*)(emb + (size_t)j * D + part * 16);
    const float4* zf = (const float4*)(z + (size_t)row * D + part * 16);
    float*        o  = zq_out + (size_t)row * D + part * 16;

    #pragma unroll
    for (int q = 0; q < 4; q++) {
        float4 e  = ef[q];
        float4 zv = zf[q];
        o[q * 4 + 0] = __fadd_rn(zv.x, __fadd_rn(e.x, -zv.x));
        o[q * 4 + 1] = __fadd_rn(zv.y, __fadd_rn(e.y, -zv.y));
        o[q * 4 + 2] = __fadd_rn(zv.z, __fadd_rn(e.z, -zv.z));
        o[q * 4 + 3] = __fadd_rn(zv.w, __fadd_rn(e.w, -zv.w));
    }
}

// ---------------------------------------------------------------------------
// Kernel 4: final loss reduction over 512 partials.
// loss = 1.25 * sum / (N*D)
// ---------------------------------------------------------------------------
__global__ void final_kernel(float* __restrict__ out) {
    __shared__ float red[256];
    red[threadIdx.x] = g_partial[threadIdx.x] + g_partial[threadIdx.x + 256];
    __syncthreads();
    #pragma unroll
    for (int st = 128; st > 0; st >>= 1) {
        if (threadIdx.x < st) red[threadIdx.x] += red[threadIdx.x + st];
        __syncthreads();
    }
    if (threadIdx.x == 0)
        out[0] = 1.25f * red[0] / (float)(N_ROWS * D);
}

// ---------------------------------------------------------------------------
// Launch: out layout = [loss(1) | z_q(N_ROWS*D) | indices(N_ROWS)] fp32
// ---------------------------------------------------------------------------
extern "C" void kernel_launch(void* const* d_in, const int* in_sizes, int n_in,
                              void* d_out, int out_size) {
    const float* z   = (const float*)d_in[0];
    const float* emb = (const float*)d_in[1];
    float* out     = (float*)d_out;
    float* zq_out  = out + 1;
    float* idx_out = out + 1 + (size_t)N_ROWS * D;

    prep_kernel<<<4, 256>>>(emb);
    argmin_tc_kernel<<<GRID_MAIN, 256>>>(z, idx_out);
    refine_kernel<<<REFINE_BLOCKS, REFINE_THREADS>>>(z, emb, idx_out);
    gather_kernel<<<K3_BLOCKS, K3_THREADS>>>(z, emb, zq_out);
    final_kernel<<<1, 256>>>(out);
}

// round 11
// speedup vs baseline: 1.9527x; 1.6871x over previous
#include <cuda_runtime.h>
#include <cuda_fp16.h>
#include <cstdint>

#define N_ROWS 65536
#define D      64
#define NE     1024
#define M_TILE 128                     // rows per CTA (8 warps x m16)
#define NC     64                      // codes per chunk
#define NUM_CHUNKS (NE / NC)           // 16
#define GRID_MAIN (N_ROWS / M_TILE)    // 512
#define GAP_THRESH 1e-4f
#define REFINE_BLOCKS 256
#define REFINE_THREADS 256
#define K3_THREADS 256
#define K3_BLOCKS  (N_ROWS * 8 / K3_THREADS)   // 8 threads/row -> 2048
#define BSTRIDE 72                     // padded smem row stride (elems) = 144 B
#define INV256  0.00390625f

// ---------------- scratch (no allocations allowed) ----------------
__device__ float g_e2[NE];
__device__ __align__(16) __half g_ef16[NE * D];   // e * 256 in fp16
__device__ int   g_idx[N_ROWS];
__device__ float g_partial[GRID_MAIN];
__device__ int   g_flag_cnt;
__device__ int   g_flag_rows[N_ROWS];

// ---------------- helpers ----------------
__device__ __forceinline__ uint32_t smem_u32(const void* p) {
    uint32_t a;
    asm("{ .reg .u64 t; cvta.to.shared.u64 t, %1; cvt.u32.u64 %0, t; }"
        : "=r"(a) : "l"(p));
    return a;
}
__device__ __forceinline__ uint32_t hpair(__half a, __half b) {
    __half2 t(a, b);                   // a = low 16 bits
    return *reinterpret_cast<uint32_t*>(&t);
}
__device__ __forceinline__ void mma_f16(float& d0, float& d1, float& d2, float& d3,
                                        uint32_t a0, uint32_t a1, uint32_t a2, uint32_t a3,
                                        uint32_t b0, uint32_t b1) {
    asm volatile(
        "mma.sync.aligned.m16n8k16.row.col.f32.f16.f16.f32 "
        "{%0,%1,%2,%3}, {%4,%5,%6,%7}, {%8,%9}, {%0,%1,%2,%3};"
        : "+f"(d0), "+f"(d1), "+f"(d2), "+f"(d3)
        : "r"(a0), "r"(a1), "r"(a2), "r"(a3), "r"(b0), "r"(b1));
}
__device__ __forceinline__ void ldsm_x2(uint32_t& r0, uint32_t& r1, uint32_t addr) {
    asm volatile("ldmatrix.sync.aligned.m8n8.x2.shared.b16 {%0,%1}, [%2];"
                 : "=r"(r0), "=r"(r1) : "r"(addr));
}
// merge two (best, best2, idx) candidate sets (union top-2), min-index tiebreak
__device__ __forceinline__ void merge_top2(float& b, float& b2, int& i, int off) {
    float ob  = __shfl_xor_sync(0xffffffffu, b,  off);
    float ob2 = __shfl_xor_sync(0xffffffffu, b2, off);
    int   oi  = __shfl_xor_sync(0xffffffffu, i,  off);
    int   ni  = (ob < b || (ob == b && oi < i)) ? oi : i;
    float nb2 = fminf(fmaxf(b, ob), fminf(b2, ob2));
    b  = fminf(b, ob);
    b2 = nb2;
    i  = ni;
}

// ---------------------------------------------------------------------------
// Kernel 1: prep: e2 (fp32) + fp16 e*256 (|e|<=1/256 -> in [-1,1], rel err
// 2^-11, 8x better than bf16). + reset flag counter.
// ---------------------------------------------------------------------------
__global__ void prep_kernel(const float* __restrict__ emb) {
    int j = blockIdx.x * blockDim.x + threadIdx.x;
    if (j == 0) g_flag_cnt = 0;
    if (j < NE) {
        const float* e = emb + (size_t)j * D;
        float s = 0.f;
        #pragma unroll
        for (int k = 0; k < D; k++) {
            float v = e[k];
            s += v * v;
            g_ef16[j * D + k] = __float2half_rn(v * 256.0f);
        }
        g_e2[j] = s;
    }
}

// ---------------------------------------------------------------------------
// Kernel 2: HMMA argmin via mma.sync m16n8k16 fp16.
// dot*256 = (Zhi + Zlo) . (E*256); z 2-plane fp16 (residual ~1e-6/elem),
// e single-plane fp16. 8 MMAs + 4 ldsm per n-tile. sigma(delta d) ~7e-6;
// GAP=1e-4=14sigma -> ~0.65% rows flagged for exact refine.
// ---------------------------------------------------------------------------
__global__ __launch_bounds__(256, 2)
void argmin_tc_kernel(const float* __restrict__ z,
                      float* __restrict__ idx_out_f) {
    __shared__ __align__(16) __half sB[NC * BSTRIDE];  // 9.2 KB
    __shared__ float sE2[NC];
    __shared__ float sLoss[8];

    int tid  = threadIdx.x;
    int wid  = tid >> 5;
    int lane = tid & 31;
    int grp  = lane >> 2;         // 0..7  (row within tile)
    int c    = lane & 3;          // 0..3  (pair column)

    // ---- A fragments (hi/lo fp16) straight from gmem; z2 via group shfl ----
    int rbase = blockIdx.x * M_TILE + wid * 16;
    int r0 = rbase + grp;         // rows grp and grp+8 of this warp's m16 tile
    uint32_t ahi[16], alo[16];
    float z2_0 = 0.f, z2_1 = 0.f;
    {
        const float* zr0 = z + (size_t)r0 * D;
        const float* zr1 = zr0 + 8 * D;
        #pragma unroll
        for (int t = 0; t < 4; t++) {
            float2 p0 = *(const float2*)(zr0 + 16 * t + 2 * c);
            float2 p1 = *(const float2*)(zr1 + 16 * t + 2 * c);
            float2 p2 = *(const float2*)(zr0 + 16 * t + 8 + 2 * c);
            float2 p3 = *(const float2*)(zr1 + 16 * t + 8 + 2 * c);
            z2_0 += p0.x * p0.x + p0.y * p0.y + p2.x * p2.x + p2.y * p2.y;
            z2_1 += p1.x * p1.x + p1.y * p1.y + p3.x * p3.x + p3.y * p3.y;
            float2 ps[4] = {p0, p1, p2, p3};
            #pragma unroll
            for (int u = 0; u < 4; u++) {
                __half hx = __float2half_rn(ps[u].x);
                __half hy = __float2half_rn(ps[u].y);
                ahi[t * 4 + u] = hpair(hx, hy);
                alo[t * 4 + u] = hpair(
                    __float2half_rn(ps[u].x - __half2float(hx)),
                    __float2half_rn(ps[u].y - __half2float(hy)));
            }
        }
        z2_0 += __shfl_xor_sync(0xffffffffu, z2_0, 1);
        z2_0 += __shfl_xor_sync(0xffffffffu, z2_0, 2);
        z2_1 += __shfl_xor_sync(0xffffffffu, z2_1, 1);
        z2_1 += __shfl_xor_sync(0xffffffffu, z2_1, 2);
    }

    float b0 = 3.402823466e38f, b20 = 3.402823466e38f;  // row r0
    float b1 = 3.402823466e38f, b21 = 3.402823466e38f;  // row r0+8
    int   i0 = 0, i1 = 0;

    uint32_t sb = smem_u32(sB);
    int ll = lane & 15;
    uint32_t lrow = (uint32_t)(ll & 7) * (BSTRIDE * 2) + ((uint32_t)(ll >> 3)) * 16;

    for (int ch = 0; ch < NUM_CHUNKS; ch++) {
        int cbase = ch * NC;
        __syncthreads();
        // ---- stage B chunk + e2 ----
        {
            int row = tid >> 2, q = tid & 3;     // 64 rows x 4 quarters
            const uint4* sh = (const uint4*)(g_ef16 + (size_t)(cbase + row) * D + q * 16);
            uint4* dh = (uint4*)(sB + row * BSTRIDE + q * 16);
            dh[0] = sh[0]; dh[1] = sh[1];
            if (tid < NC) sE2[tid] = g_e2[cbase + tid];
        }
        __syncthreads();

        #pragma unroll 1
        for (int nt = 0; nt < NC / 8; nt++) {
            float d0 = 0.f, d1 = 0.f, d2 = 0.f, d3 = 0.f;
            uint32_t nbase = (uint32_t)(nt * 8) * (BSTRIDE * 2) + lrow;
            #pragma unroll
            for (int t = 0; t < 4; t++) {
                uint32_t bh0, bh1;
                ldsm_x2(bh0, bh1, sb + nbase + t * 32);
                mma_f16(d0, d1, d2, d3, ahi[t*4+0], ahi[t*4+1], ahi[t*4+2], ahi[t*4+3], bh0, bh1);
                mma_f16(d0, d1, d2, d3, alo[t*4+0], alo[t*4+1], alo[t*4+2], alo[t*4+3], bh0, bh1);
            }
            // ---- epilogue: dd = (z2+e2) - 2*(dscaled/256) ----
            int ca = cbase + nt * 8 + 2 * c;
            float ea = sE2[nt * 8 + 2 * c];
            float eb = sE2[nt * 8 + 2 * c + 1];
            float dd0 = (z2_0 + ea) - 2.f * (d0 * INV256);
            float dd1 = (z2_0 + eb) - 2.f * (d1 * INV256);
            float dd2 = (z2_1 + ea) - 2.f * (d2 * INV256);
            float dd3 = (z2_1 + eb) - 2.f * (d3 * INV256);
            if (dd0 < b0) { b20 = b0; b0 = dd0; i0 = ca; }
            else if (dd0 < b20) b20 = dd0;
            if (dd1 < b0) { b20 = b0; b0 = dd1; i0 = ca + 1; }
            else if (dd1 < b20) b20 = dd1;
            if (dd2 < b1) { b21 = b1; b1 = dd2; i1 = ca; }
            else if (dd2 < b21) b21 = dd2;
            if (dd3 < b1) { b21 = b1; b1 = dd3; i1 = ca + 1; }
            else if (dd3 < b21) b21 = dd3;
        }
    }

    // ---- merge across the 4 lanes of each row group ----
    merge_top2(b0, b20, i0, 1); merge_top2(b0, b20, i0, 2);
    merge_top2(b1, b21, i1, 1); merge_top2(b1, b21, i1, 2);

    if (c == 0) {
        int r1 = r0 + 8;
        g_idx[r0] = i0;            g_idx[r1] = i1;
        idx_out_f[r0] = (float)i0; idx_out_f[r1] = (float)i1;
        if (b20 - b0 < GAP_THRESH) { int s = atomicAdd(&g_flag_cnt, 1); g_flag_rows[s] = r0; }
        if (b21 - b1 < GAP_THRESH) { int s = atomicAdd(&g_flag_cnt, 1); g_flag_rows[s] = r1; }
    }

    // ---- loss partial: sum of bestd over the CTA's 128 rows ----
    float v = (c == 0) ? (b0 + b1) : 0.f;
    #pragma unroll
    for (int o = 16; o > 0; o >>= 1) v += __shfl_down_sync(0xffffffffu, v, o);
    if (lane == 0) sLoss[wid] = v;
    __syncthreads();
    if (tid == 0) {
        float s = 0.f;
        #pragma unroll
        for (int w = 0; w < 8; w++) s += sLoss[w];
        g_partial[blockIdx.x] = s;
    }
}

// ---------------------------------------------------------------------------
// Kernel 2b: refine flagged rows (exact Kahan fp32 dots). 256 threads,
// 4 codes/thread. Rewrites g_idx + idx_out only.
// ---------------------------------------------------------------------------
__global__ __launch_bounds__(REFINE_THREADS)
void refine_kernel(const float* __restrict__ z,
                   const float* __restrict__ emb,
                   float* __restrict__ idx_out_f) {
    __shared__ float sz[D];
    __shared__ float sd[REFINE_THREADS];
    __shared__ int   si[REFINE_THREADS];

    int cnt = g_flag_cnt;
    for (int w = blockIdx.x; w < cnt; w += gridDim.x) {
        int row = g_flag_rows[w];

        __syncthreads();
        if (threadIdx.x < D) sz[threadIdx.x] = z[(size_t)row * D + threadIdx.x];
        __syncthreads();

        float z2 = 0.f;
        #pragma unroll
        for (int k = 0; k < D; k++) z2 += sz[k] * sz[k];

        float bestd = 3.402823466e38f;
        int   besti = NE;

        for (int j = threadIdx.x; j < NE; j += REFINE_THREADS) {
            const float4* e = (const float4*)(emb + (size_t)j * D);
            float4 ev[16];
            #pragma unroll
            for (int q = 0; q < 16; q++) ev[q] = e[q];

            float s = 0.f, cc = 0.f;
            #pragma unroll
            for (int q = 0; q < 16; q++) {
                float el[4] = {ev[q].x, ev[q].y, ev[q].z, ev[q].w};
                #pragma unroll
                for (int u = 0; u < 4; u++) {
                    float p = __fmul_rn(sz[q * 4 + u], el[u]);
                    float y = __fadd_rn(p, -cc);
                    float t = __fadd_rn(s, y);
                    cc = __fadd_rn(__fadd_rn(t, -s), -y);
                    s = t;
                }
            }
            float dot = __fadd_rn(s, cc);
            float dd  = __fadd_rn(__fadd_rn(z2, g_e2[j]), -2.f * dot);
            if (dd < bestd || (dd == bestd && j < besti)) { bestd = dd; besti = j; }
        }

        sd[threadIdx.x] = bestd;
        si[threadIdx.x] = besti;
        __syncthreads();
        #pragma unroll
        for (int st = REFINE_THREADS / 2; st > 0; st >>= 1) {
            if (threadIdx.x < st) {
                float od = sd[threadIdx.x + st];
                int   oi = si[threadIdx.x + st];
                if (od < sd[threadIdx.x] ||
                    (od == sd[threadIdx.x] && oi < si[threadIdx.x])) {
                    sd[threadIdx.x] = od;
                    si[threadIdx.x] = oi;
                }
            }
            __syncthreads();
        }
        if (threadIdx.x == 0) {
            g_idx[row]     = si[0];
            idx_out_f[row] = (float)si[0];
        }
        __syncthreads();
    }
}

// ---------------------------------------------------------------------------
// Kernel 3: zq gather, 8 threads/row (2 float4 each) for latency hiding.
// out = z + (e - z) (straight-through). zq_out 4B-aligned -> scalar stores.
// ---------------------------------------------------------------------------
__global__ __launch_bounds__(K3_THREADS)
void gather_kernel(const float* __restrict__ z,
                   const float* __restrict__ emb,
                   float* __restrict__ zq_out) {
    int gt   = blockIdx.x * K3_THREADS + threadIdx.x;
    int row  = gt >> 3;
    int part = gt & 7;
    int j    = g_idx[row];

    const float4* ef = (const float4*)(emb + (size_t)j * D + part * 8);
    const float4* zf = (const float4*)(z + (size_t)row * D + part * 8);
    float*        o  = zq_out + (size_t)row * D + part * 8;

    #pragma unroll
    for (int q = 0; q < 2; q++) {
        float4 e  = ef[q];
        float4 zv = zf[q];
        o[q * 4 + 0] = __fadd_rn(zv.x, __fadd_rn(e.x, -zv.x));
        o[q * 4 + 1] = __fadd_rn(zv.y, __fadd_rn(e.y, -zv.y));
        o[q * 4 + 2] = __fadd_rn(zv.z, __fadd_rn(e.z, -zv.z));
        o[q * 4 + 3] = __fadd_rn(zv.w, __fadd_rn(e.w, -zv.w));
    }
}

// ---------------------------------------------------------------------------
// Kernel 4: final loss reduction over 512 partials.
// loss = 1.25 * sum / (N*D)
// ---------------------------------------------------------------------------
__global__ void final_kernel(float* __restrict__ out) {
    __shared__ float red[256];
    red[threadIdx.x] = g_partial[threadIdx.x] + g_partial[threadIdx.x + 256];
    __syncthreads();
    #pragma unroll
    for (int st = 128; st > 0; st >>= 1) {
        if (threadIdx.x < st) red[threadIdx.x] += red[threadIdx.x + st];
        __syncthreads();
    }
    if (threadIdx.x == 0)
        out[0] = 1.25f * red[0] / (float)(N_ROWS * D);
}

// ---------------------------------------------------------------------------
// Launch: out layout = [loss(1) | z_q(N_ROWS*D) | indices(N_ROWS)] fp32
// ---------------------------------------------------------------------------
extern "C" void kernel_launch(void* const* d_in, const int* in_sizes, int n_in,
                              void* d_out, int out_size) {
    const float* z   = (const float*)d_in[0];
    const float* emb = (const float*)d_in[1];
    float* out     = (float*)d_out;
    float* zq_out  = out + 1;
    float* idx_out = out + 1 + (size_t)N_ROWS * D;

    prep_kernel<<<4, 256>>>(emb);
    argmin_tc_kernel<<<GRID_MAIN, 256>>>(z, idx_out);
    refine_kernel<<<REFINE_BLOCKS, REFINE_THREADS>>>(z, emb, idx_out);
    gather_kernel<<<K3_BLOCKS, K3_THREADS>>>(z, emb, zq_out);
    final_kernel<<<1, 256>>>(out);
}

// round 12
// speedup vs baseline: 2.0853x; 1.0679x over previous
#include <cuda_runtime.h>
#include <cuda_fp16.h>
#include <cstdint>

#define N_ROWS 65536
#define D      64
#define NE     1024
#define M_TILE 128                     // rows per CTA (8 warps x m16)
#define NC     64                      // codes per chunk
#define NUM_CHUNKS (NE / NC)           // 16
#define GRID_MAIN (N_ROWS / M_TILE)    // 512
#define GAP_THRESH 1.5e-4f
#define REFINE_BLOCKS 256
#define REFINE_THREADS 256
#define K3_THREADS 256
#define K3_BLOCKS  (N_ROWS * 8 / K3_THREADS)   // 8 threads/row -> 2048
#define BSTRIDE 72                     // padded smem row stride (elems) = 144 B
#define INV256  0.00390625f

// ---------------- scratch (no allocations allowed) ----------------
__device__ float g_e2[NE];
__device__ __align__(16) __half g_ef16[NE * D];   // e * 256 in fp16
__device__ int   g_idx[N_ROWS];
__device__ float g_partial[GRID_MAIN];
__device__ int   g_flag_cnt;
__device__ int   g_flag_rows[N_ROWS];

// ---------------- helpers ----------------
__device__ __forceinline__ uint32_t smem_u32(const void* p) {
    uint32_t a;
    asm("{ .reg .u64 t; cvta.to.shared.u64 t, %1; cvt.u32.u64 %0, t; }"
        : "=r"(a) : "l"(p));
    return a;
}
__device__ __forceinline__ uint32_t hpair(__half a, __half b) {
    __half2 t(a, b);                   // a = low 16 bits
    return *reinterpret_cast<uint32_t*>(&t);
}
__device__ __forceinline__ void mma_f16(float& d0, float& d1, float& d2, float& d3,
                                        uint32_t a0, uint32_t a1, uint32_t a2, uint32_t a3,
                                        uint32_t b0, uint32_t b1) {
    asm volatile(
        "mma.sync.aligned.m16n8k16.row.col.f32.f16.f16.f32 "
        "{%0,%1,%2,%3}, {%4,%5,%6,%7}, {%8,%9}, {%0,%1,%2,%3};"
        : "+f"(d0), "+f"(d1), "+f"(d2), "+f"(d3)
        : "r"(a0), "r"(a1), "r"(a2), "r"(a3), "r"(b0), "r"(b1));
}
__device__ __forceinline__ void ldsm_x2(uint32_t& r0, uint32_t& r1, uint32_t addr) {
    asm volatile("ldmatrix.sync.aligned.m8n8.x2.shared.b16 {%0,%1}, [%2];"
                 : "=r"(r0), "=r"(r1) : "r"(addr));
}
// merge two (best, best2, idx) candidate sets (union top-2), min-index tiebreak
__device__ __forceinline__ void merge_top2(float& b, float& b2, int& i, int off) {
    float ob  = __shfl_xor_sync(0xffffffffu, b,  off);
    float ob2 = __shfl_xor_sync(0xffffffffu, b2, off);
    int   oi  = __shfl_xor_sync(0xffffffffu, i,  off);
    int   ni  = (ob < b || (ob == b && oi < i)) ? oi : i;
    float nb2 = fminf(fmaxf(b, ob), fminf(b2, ob2));
    b  = fminf(b, ob);
    b2 = nb2;
    i  = ni;
}

// ---------------------------------------------------------------------------
// Kernel 1: prep: e2 (fp32) + fp16 e*256 (|e|<=1/256 -> in [-1,1], rel err
// 2^-12). + reset flag counter.
// ---------------------------------------------------------------------------
__global__ void prep_kernel(const float* __restrict__ emb) {
    int j = blockIdx.x * blockDim.x + threadIdx.x;
    if (j == 0) g_flag_cnt = 0;
    if (j < NE) {
        const float* e = emb + (size_t)j * D;
        float s = 0.f;
        #pragma unroll
        for (int k = 0; k < D; k++) {
            float v = e[k];
            s += v * v;
            g_ef16[j * D + k] = __float2half_rn(v * 256.0f);
        }
        g_e2[j] = s;
    }
}

// ---------------------------------------------------------------------------
// Kernel 2: HMMA argmin via mma.sync m16n8k16 fp16, SINGLE-plane both sides.
// dot*256 = Z16 . (E*256). 4 MMAs + 4 ldsm per n-tile (half of round 11).
// sigma(delta d) ~9.5e-6 (e-quant 8.8e-6 + z-quant 3.5e-6); GAP=1.5e-4 =
// ~11 sigma_pair -> ~1% rows flagged, exact Kahan refine decides those.
// ---------------------------------------------------------------------------
__global__ __launch_bounds__(256, 2)
void argmin_tc_kernel(const float* __restrict__ z,
                      float* __restrict__ idx_out_f) {
    __shared__ __align__(16) __half sB[NC * BSTRIDE];  // 9.2 KB
    __shared__ float sE2[NC];
    __shared__ float sLoss[8];

    int tid  = threadIdx.x;
    int wid  = tid >> 5;
    int lane = tid & 31;
    int grp  = lane >> 2;         // 0..7  (row within tile)
    int c    = lane & 3;          // 0..3  (pair column)

    // ---- A fragments (single-plane fp16) from gmem; z2 via group shfl ----
    int rbase = blockIdx.x * M_TILE + wid * 16;
    int r0 = rbase + grp;         // rows grp and grp+8 of this warp's m16 tile
    uint32_t af[16];
    float z2_0 = 0.f, z2_1 = 0.f;
    {
        const float* zr0 = z + (size_t)r0 * D;
        const float* zr1 = zr0 + 8 * D;
        #pragma unroll
        for (int t = 0; t < 4; t++) {
            float2 p0 = *(const float2*)(zr0 + 16 * t + 2 * c);
            float2 p1 = *(const float2*)(zr1 + 16 * t + 2 * c);
            float2 p2 = *(const float2*)(zr0 + 16 * t + 8 + 2 * c);
            float2 p3 = *(const float2*)(zr1 + 16 * t + 8 + 2 * c);
            z2_0 += p0.x * p0.x + p0.y * p0.y + p2.x * p2.x + p2.y * p2.y;
            z2_1 += p1.x * p1.x + p1.y * p1.y + p3.x * p3.x + p3.y * p3.y;
            af[t * 4 + 0] = hpair(__float2half_rn(p0.x), __float2half_rn(p0.y));
            af[t * 4 + 1] = hpair(__float2half_rn(p1.x), __float2half_rn(p1.y));
            af[t * 4 + 2] = hpair(__float2half_rn(p2.x), __float2half_rn(p2.y));
            af[t * 4 + 3] = hpair(__float2half_rn(p3.x), __float2half_rn(p3.y));
        }
        z2_0 += __shfl_xor_sync(0xffffffffu, z2_0, 1);
        z2_0 += __shfl_xor_sync(0xffffffffu, z2_0, 2);
        z2_1 += __shfl_xor_sync(0xffffffffu, z2_1, 1);
        z2_1 += __shfl_xor_sync(0xffffffffu, z2_1, 2);
    }

    float b0 = 3.402823466e38f, b20 = 3.402823466e38f;  // row r0
    float b1 = 3.402823466e38f, b21 = 3.402823466e38f;  // row r0+8
    int   i0 = 0, i1 = 0;

    uint32_t sb = smem_u32(sB);
    int ll = lane & 15;
    uint32_t lrow = (uint32_t)(ll & 7) * (BSTRIDE * 2) + ((uint32_t)(ll >> 3)) * 16;

    for (int ch = 0; ch < NUM_CHUNKS; ch++) {
        int cbase = ch * NC;
        __syncthreads();
        // ---- stage B chunk + e2 ----
        {
            int row = tid >> 2, q = tid & 3;     // 64 rows x 4 quarters
            const uint4* sh = (const uint4*)(g_ef16 + (size_t)(cbase + row) * D + q * 16);
            uint4* dh = (uint4*)(sB + row * BSTRIDE + q * 16);
            dh[0] = sh[0]; dh[1] = sh[1];
            if (tid < NC) sE2[tid] = g_e2[cbase + tid];
        }
        __syncthreads();

        #pragma unroll 1
        for (int nt = 0; nt < NC / 8; nt++) {
            float d0 = 0.f, d1 = 0.f, d2 = 0.f, d3 = 0.f;
            uint32_t nbase = (uint32_t)(nt * 8) * (BSTRIDE * 2) + lrow;
            #pragma unroll
            for (int t = 0; t < 4; t++) {
                uint32_t bh0, bh1;
                ldsm_x2(bh0, bh1, sb + nbase + t * 32);
                mma_f16(d0, d1, d2, d3, af[t*4+0], af[t*4+1], af[t*4+2], af[t*4+3], bh0, bh1);
            }
            // ---- epilogue: dd = (z2+e2) - 2*(dscaled/256) ----
            int ca = cbase + nt * 8 + 2 * c;
            float ea = sE2[nt * 8 + 2 * c];
            float eb = sE2[nt * 8 + 2 * c + 1];
            float dd0 = (z2_0 + ea) - 2.f * (d0 * INV256);
            float dd1 = (z2_0 + eb) - 2.f * (d1 * INV256);
            float dd2 = (z2_1 + ea) - 2.f * (d2 * INV256);
            float dd3 = (z2_1 + eb) - 2.f * (d3 * INV256);
            if (dd0 < b0) { b20 = b0; b0 = dd0; i0 = ca; }
            else if (dd0 < b20) b20 = dd0;
            if (dd1 < b0) { b20 = b0; b0 = dd1; i0 = ca + 1; }
            else if (dd1 < b20) b20 = dd1;
            if (dd2 < b1) { b21 = b1; b1 = dd2; i1 = ca; }
            else if (dd2 < b21) b21 = dd2;
            if (dd3 < b1) { b21 = b1; b1 = dd3; i1 = ca + 1; }
            else if (dd3 < b21) b21 = dd3;
        }
    }

    // ---- merge across the 4 lanes of each row group ----
    merge_top2(b0, b20, i0, 1); merge_top2(b0, b20, i0, 2);
    merge_top2(b1, b21, i1, 1); merge_top2(b1, b21, i1, 2);

    if (c == 0) {
        int r1 = r0 + 8;
        g_idx[r0] = i0;            g_idx[r1] = i1;
        idx_out_f[r0] = (float)i0; idx_out_f[r1] = (float)i1;
        if (b20 - b0 < GAP_THRESH) { int s = atomicAdd(&g_flag_cnt, 1); g_flag_rows[s] = r0; }
        if (b21 - b1 < GAP_THRESH) { int s = atomicAdd(&g_flag_cnt, 1); g_flag_rows[s] = r1; }
    }

    // ---- loss partial: sum of bestd over the CTA's 128 rows ----
    float v = (c == 0) ? (b0 + b1) : 0.f;
    #pragma unroll
    for (int o = 16; o > 0; o >>= 1) v += __shfl_down_sync(0xffffffffu, v, o);
    if (lane == 0) sLoss[wid] = v;
    __syncthreads();
    if (tid == 0) {
        float s = 0.f;
        #pragma unroll
        for (int w = 0; w < 8; w++) s += sLoss[w];
        g_partial[blockIdx.x] = s;
    }
}

// ---------------------------------------------------------------------------
// Kernel 2b: refine flagged rows (exact Kahan fp32 dots). 256 threads,
// 4 codes/thread. Rewrites g_idx + idx_out only.
// ---------------------------------------------------------------------------
__global__ __launch_bounds__(REFINE_THREADS)
void refine_kernel(const float* __restrict__ z,
                   const float* __restrict__ emb,
                   float* __restrict__ idx_out_f) {
    __shared__ float sz[D];
    __shared__ float sd[REFINE_THREADS];
    __shared__ int   si[REFINE_THREADS];

    int cnt = g_flag_cnt;
    for (int w = blockIdx.x; w < cnt; w += gridDim.x) {
        int row = g_flag_rows[w];

        __syncthreads();
        if (threadIdx.x < D) sz[threadIdx.x] = z[(size_t)row * D + threadIdx.x];
        __syncthreads();

        float z2 = 0.f;
        #pragma unroll
        for (int k = 0; k < D; k++) z2 += sz[k] * sz[k];

        float bestd = 3.402823466e38f;
        int   besti = NE;

        for (int j = threadIdx.x; j < NE; j += REFINE_THREADS) {
            const float4* e = (const float4*)(emb + (size_t)j * D);
            float4 ev[16];
            #pragma unroll
            for (int q = 0; q < 16; q++) ev[q] = e[q];

            float s = 0.f, cc = 0.f;
            #pragma unroll
            for (int q = 0; q < 16; q++) {
                float el[4] = {ev[q].x, ev[q].y, ev[q].z, ev[q].w};
                #pragma unroll
                for (int u = 0; u < 4; u++) {
                    float p = __fmul_rn(sz[q * 4 + u], el[u]);
                    float y = __fadd_rn(p, -cc);
                    float t = __fadd_rn(s, y);
                    cc = __fadd_rn(__fadd_rn(t, -s), -y);
                    s = t;
                }
            }
            float dot = __fadd_rn(s, cc);
            float dd  = __fadd_rn(__fadd_rn(z2, g_e2[j]), -2.f * dot);
            if (dd < bestd || (dd == bestd && j < besti)) { bestd = dd; besti = j; }
        }

        sd[threadIdx.x] = bestd;
        si[threadIdx.x] = besti;
        __syncthreads();
        #pragma unroll
        for (int st = REFINE_THREADS / 2; st > 0; st >>= 1) {
            if (threadIdx.x < st) {
                float od = sd[threadIdx.x + st];
                int   oi = si[threadIdx.x + st];
                if (od < sd[threadIdx.x] ||
                    (od == sd[threadIdx.x] && oi < si[threadIdx.x])) {
                    sd[threadIdx.x] = od;
                    si[threadIdx.x] = oi;
                }
            }
            __syncthreads();
        }
        if (threadIdx.x == 0) {
            g_idx[row]     = si[0];
            idx_out_f[row] = (float)si[0];
        }
        __syncthreads();
    }
}

// ---------------------------------------------------------------------------
// Kernel 3: zq gather, 8 threads/row (2 float4 each) for latency hiding.
// out = z + (e - z) (straight-through). zq_out 4B-aligned -> scalar stores.
// ---------------------------------------------------------------------------
__global__ __launch_bounds__(K3_THREADS)
void gather_kernel(const float* __restrict__ z,
                   const float* __restrict__ emb,
                   float* __restrict__ zq_out) {
    int gt   = blockIdx.x * K3_THREADS + threadIdx.x;
    int row  = gt >> 3;
    int part = gt & 7;
    int j    = g_idx[row];

    const float4* ef = (const float4*)(emb + (size_t)j * D + part * 8);
    const float4* zf = (const float4*)(z + (size_t)row * D + part * 8);
    float*        o  = zq_out + (size_t)row * D + part * 8;

    #pragma unroll
    for (int q = 0; q < 2; q++) {
        float4 e  = ef[q];
        float4 zv = zf[q];
        o[q * 4 + 0] = __fadd_rn(zv.x, __fadd_rn(e.x, -zv.x));
        o[q * 4 + 1] = __fadd_rn(zv.y, __fadd_rn(e.y, -zv.y));
        o[q * 4 + 2] = __fadd_rn(zv.z, __fadd_rn(e.z, -zv.z));
        o[q * 4 + 3] = __fadd_rn(zv.w, __fadd_rn(e.w, -zv.w));
    }
}

// ---------------------------------------------------------------------------
// Kernel 4: final loss reduction over 512 partials.
// loss = 1.25 * sum / (N*D)
// ---------------------------------------------------------------------------
__global__ void final_kernel(float* __restrict__ out) {
    __shared__ float red[256];
    red[threadIdx.x] = g_partial[threadIdx.x] + g_partial[threadIdx.x + 256];
    __syncthreads();
    #pragma unroll
    for (int st = 128; st > 0; st >>= 1) {
        if (threadIdx.x < st) red[threadIdx.x] += red[threadIdx.x + st];
        __syncthreads();
    }
    if (threadIdx.x == 0)
        out[0] = 1.25f * red[0] / (float)(N_ROWS * D);
}

// ---------------------------------------------------------------------------
// Launch: out layout = [loss(1) | z_q(N_ROWS*D) | indices(N_ROWS)] fp32
// ---------------------------------------------------------------------------
extern "C" void kernel_launch(void* const* d_in, const int* in_sizes, int n_in,
                              void* d_out, int out_size) {
    const float* z   = (const float*)d_in[0];
    const float* emb = (const float*)d_in[1];
    float* out     = (float*)d_out;
    float* zq_out  = out + 1;
    float* idx_out = out + 1 + (size_t)N_ROWS * D;

    prep_kernel<<<4, 256>>>(emb);
    argmin_tc_kernel<<<GRID_MAIN, 256>>>(z, idx_out);
    refine_kernel<<<REFINE_BLOCKS, REFINE_THREADS>>>(z, emb, idx_out);
    gather_kernel<<<K3_BLOCKS, K3_THREADS>>>(z, emb, zq_out);
    final_kernel<<<1, 256>>>(out);
}